// round 10
// baseline (speedup 1.0000x reference)
#include <cuda_runtime.h>
#include <cuda_bf16.h>

// PositionEncoding: out[b,s,:] = is_class ? E_class[class_id] : sincos(v * 2^i * pi)
// B=64, S=8192, 32 levels (E=64), CLASS_NUM=4096.
//
// R9 = R8 body (best flushed time: compute into output regs, predicated
// @P LDG.128 overwrite, __stcs store; regs<=32) made PERSISTENT:
//   grid = 148 SMs x 8 CTAs = 1184 -> exactly one wave (was ~7 waves at
//   grid=8192; each transition ~2360 cyc + tail imbalance = the residual gap
//   between our 23us and the ~17.5us LTS-cap floor).
//   Stride 1184*256 = 303104 is divisible by 16, so the per-thread slot t
//   (and scale_e) is loop-invariant: hoisted out of the work loop.
//
// Angle math (FP64-free "turns"): angle for level i is exactly 2^i * a0 with
// a0 = fl32(v*pi_f) (pow2 scaling commutes with fp32 rounding). u =
// frac(a0*(1/2pi)*2^i) via two-float 1/2pi (~47 bits); pow2 scale and frac
// exact in fp32 -> angle err ~2.4e-5 rad (x2 after one doubling) << 1e-3 tol.

#define NTOK    (64 * 8192)     // 524288 tokens
#define UNROLL  4               // tokens per work item
#define NBLK    1184            // 148 SMs * 8 resident CTAs: one wave
#define NTHREAD 256

__global__ __launch_bounds__(NTHREAD, 8)
void pos_enc_kernel(const float4* __restrict__ values4,    // [NTOK/4]
                    const float4* __restrict__ E_class,    // [4096][16] float4
                    const int4*  __restrict__ class_ids4,  // [NTOK/4]
                    const int4*  __restrict__ is_class4,   // [NTOK/4]
                    float4* __restrict__ out)               // [NTOK][16] float4
{
    const unsigned total  = (NTOK / UNROLL) * 16u;   // 2,097,152 work items
    const unsigned stride = NBLK * NTHREAD;          // 303,104 (== 0 mod 16)
    unsigned gid = blockIdx.x * NTHREAD + threadIdx.x;

    // slot t is invariant across the stride loop (stride % 16 == 0)
    const unsigned t = gid & 15u;                    // levels 2t, 2t+1

    // two-float 1/(2pi): C_HI + C_LO ~ 47 bits (folded at compile time)
    constexpr double INV2PI_D = 0.15915494309189533577;
    constexpr float  C_HI = (float)INV2PI_D;
    constexpr float  C_LO = (float)(INV2PI_D - (double)C_HI);
    const float PI_F     = 3.14159265358979323846f;  // rounds to pi_f32
    const float TWO_PI_F = 6.28318530717958647693f;

    // 2^(2t) as exact fp32 via exponent bits (loop-invariant)
    const float scale_e = __uint_as_float((127u + 2u * t) << 23);

    for (unsigned idx = gid; idx < total; idx += stride) {
        unsigned grp  = idx >> 4;          // token group (4 tokens)
        unsigned tok0 = grp * UNROLL;

        // ---- 3 vector loads cover all 12 per-token scalars ----
        float4 v4 = __ldg(&values4[grp]);
        int4   c4 = __ldg(&class_ids4[grp]);
        int4   m4 = __ldg(&is_class4[grp]);

        float v[UNROLL]  = { v4.x, v4.y, v4.z, v4.w };
        int   cid[UNROLL]= { c4.x, c4.y, c4.z, c4.w };
        int   ic[UNROLL] = { m4.x, m4.y, m4.z, m4.w };

        // ---- compute all slots into output regs (unconditional) ----
        float4 o[UNROLL];
#pragma unroll
        for (int j = 0; j < UNROLL; j++) {
            float a0   = v[j] * PI_F;                 // fl32(v*pi) — matches ref
            float s_hi = a0 * C_HI;
            float perr = fmaf(a0, C_HI, -s_hi);       // exact residual
            float s_lo = fmaf(a0, C_LO, perr);        // two-float tail (~47 bits)
            float y_hi = s_hi * scale_e;              // exact (pow2 scale)
            float y_lo = s_lo * scale_e;              // exact
            float f    = (y_hi - floorf(y_hi)) + (y_lo - floorf(y_lo));
            float w0   = f - rintf(f);                // turn in [-0.5, 0.5]

            float s0, c0;
            __sincosf(w0 * TWO_PI_F, &s0, &c0);       // level 2t
            float s1 = 2.0f * s0 * c0;                // level 2t+1 (double angle)
            float c1 = fmaf(-2.0f * s0, s0, 1.0f);
            o[j] = make_float4(s0, c0, s1, c1);
        }

        // ---- predicated gathers overwrite the SAME registers ----
#pragma unroll
        for (int j = 0; j < UNROLL; j++) {
            if (ic[j] == 1)
                o[j] = __ldg(&E_class[(unsigned)cid[j] * 16u + t]);
        }

        // ---- streaming stores (evict-first: never re-read) ----
#pragma unroll
        for (int j = 0; j < UNROLL; j++)
            __stcs(&out[(tok0 + j) * 16u + t], o[j]);
    }
}

extern "C" void kernel_launch(void* const* d_in, const int* in_sizes, int n_in,
                              void* d_out, int out_size)
{
    const float4* values4    = (const float4*)d_in[0];
    const float4* E_class    = (const float4*)d_in[1];
    const int4*   class_ids4 = (const int4*)d_in[2];
    const int4*   is_class4  = (const int4*)d_in[3];
    float4*       out        = (float4*)d_out;

    pos_enc_kernel<<<NBLK, NTHREAD>>>(values4, E_class, class_ids4, is_class4, out);
}

// round 11
// speedup vs baseline: 1.0704x; 1.0704x over previous
#include <cuda_runtime.h>
#include <cuda_bf16.h>

// PositionEncoding: out[b,s,:] = is_class ? E_class[class_id] : sincos(v * 2^i * pi)
// B=64, S=8192, 32 levels (E=64), CLASS_NUM=4096.
//
// R10 = the untested corner: EARLY gathers + BRANCHLESS merge + LOW registers,
// made register-feasible by UNROLL=2:
//   - 16 threads/token, one contiguous float4 store each (sacred 512B warp
//     stores), __stcs (load-bearing under graph replay).
//   - predicated E_class gathers issued FIRST into cls[2] (8 staging regs —
//     at UNROLL=4 this was 16 regs and killed occupancy in R7); their ~600cyc
//     L2 latency hides under the unconditional sincos compute.
//   - FSEL merge at the store; no BSSY/BSYNC anywhere.
//   - __launch_bounds__(256,8) pins regs<=32 (occ >= ~85% is law; R5-R9).
//
// Angle math (FP64-free "turns"): angle for level i is exactly 2^i * a0 with
// a0 = fl32(v*pi_f) (pow2 scaling commutes with fp32 rounding). u =
// frac(a0*(1/2pi)*2^i) via two-float 1/2pi (~47 bits); pow2 scale and frac
// exact in fp32 -> angle err ~2.4e-5 rad (x2 after one doubling) << 1e-3 tol.

#define NTOK   (64 * 8192)     // 524288 tokens
#define UNROLL 2               // tokens per thread

__global__ __launch_bounds__(256, 8)
void pos_enc_kernel(const float2* __restrict__ values2,    // [NTOK/2]
                    const float4* __restrict__ E_class,    // [4096][16] float4
                    const int2*  __restrict__ class_ids2,  // [NTOK/2]
                    const int2*  __restrict__ is_class2,   // [NTOK/2]
                    float4* __restrict__ out)               // [NTOK][16] float4
{
    unsigned gid  = blockIdx.x * 256u + threadIdx.x;
    unsigned t    = gid & 15u;          // float4 slot -> levels 2t, 2t+1
    unsigned grp  = gid >> 4;           // token pair
    unsigned tok0 = grp * UNROLL;

    // two-float 1/(2pi): C_HI + C_LO ~ 47 bits (folded at compile time)
    constexpr double INV2PI_D = 0.15915494309189533577;
    constexpr float  C_HI = (float)INV2PI_D;
    constexpr float  C_LO = (float)(INV2PI_D - (double)C_HI);
    const float PI_F     = 3.14159265358979323846f;   // rounds to pi_f32
    const float TWO_PI_F = 6.28318530717958647693f;

    // 2^(2t) as exact fp32 via exponent bits
    const float scale_e = __uint_as_float((127u + 2u * t) << 23);

    // ---- 3 vector loads cover the 6 per-token scalars ----
    float2 v2 = __ldg(&values2[grp]);
    int2   c2 = __ldg(&class_ids2[grp]);
    int2   m2 = __ldg(&is_class2[grp]);

    float v[UNROLL]  = { v2.x, v2.y };
    int   cid[UNROLL]= { c2.x, c2.y };
    int   ic[UNROLL] = { m2.x, m2.y };

    // ---- predicated gathers issued EARLY (@P LDG.128, latency hidden) ----
    float4 cls[UNROLL];
#pragma unroll
    for (int j = 0; j < UNROLL; j++) {
        if (ic[j] == 1)
            cls[j] = __ldg(&E_class[(unsigned)cid[j] * 16u + t]);
    }

    // ---- unconditional compute, FSEL merge, streaming store ----
#pragma unroll
    for (int j = 0; j < UNROLL; j++) {
        float a0   = v[j] * PI_F;                 // fl32(v*pi) — matches reference
        float s_hi = a0 * C_HI;
        float perr = fmaf(a0, C_HI, -s_hi);       // exact residual of a0*C_HI
        float s_lo = fmaf(a0, C_LO, perr);        // two-float tail, ~47 bits total
        float y_hi = s_hi * scale_e;              // exact (pow2 scale)
        float y_lo = s_lo * scale_e;              // exact
        float f    = (y_hi - floorf(y_hi)) + (y_lo - floorf(y_lo)); // exact fracs
        float w0   = f - rintf(f);                // turn in [-0.5, 0.5]

        float s0, c0;
        __sincosf(w0 * TWO_PI_F, &s0, &c0);       // level 2t
        float s1 = 2.0f * s0 * c0;                // level 2t+1 via double angle
        float c1 = fmaf(-2.0f * s0, s0, 1.0f);

        bool is_cls = (ic[j] == 1);
        float4 o;
        o.x = is_cls ? cls[j].x : s0;
        o.y = is_cls ? cls[j].y : c0;
        o.z = is_cls ? cls[j].z : s1;
        o.w = is_cls ? cls[j].w : c1;
        __stcs(&out[(tok0 + j) * 16u + t], o);    // evict-first: never re-read
    }
}

extern "C" void kernel_launch(void* const* d_in, const int* in_sizes, int n_in,
                              void* d_out, int out_size)
{
    const float2* values2    = (const float2*)d_in[0];
    const float4* E_class    = (const float4*)d_in[1];
    const int2*   class_ids2 = (const int2*)d_in[2];
    const int2*   is_class2  = (const int2*)d_in[3];
    float4*       out        = (float4*)d_out;

    const int threads = 256;
    const int total   = (NTOK / UNROLL) * 16;     // 4,194,304 threads
    const int blocks  = total / threads;          // 16384, exact
    pos_enc_kernel<<<blocks, threads>>>(values2, E_class, class_ids2, is_class2, out);
}